// round 14
// baseline (speedup 1.0000x reference)
#include <cuda_runtime.h>
#include <cuda_bf16.h>
#include <mma.h>
#include <math.h>

using namespace nvcuda;

#define BB 4
#define LL 2048
#define KK 48
#define HH 128
#define FFD 512

// bf16 weights (node + edge MLPs)
#define NB1   0
#define NB2   49152
#define NB3   65536
#define NB11  81920
#define NB12  131072
#define NB13  147456
#define NBTOT 163840
// tf32-f32 weights (FFN)
#define CWIN  0
#define CWOUT 65536
#define CWTOT 131072

__device__ __nv_bfloat16 g_wb[NBTOT];
__device__ float g_cw[CWTOT];
__device__ float g_v1[BB*LL*HH];   // h_V after node update + LN1
__device__ float g_v2[BB*LL*HH];   // h_V after FFN + LN2 + mask

#define XLD 392   // bf16 X tile row stride (elements)
#define FLD 132   // f32 staging row stride
#define HLD 136   // bf16 H tile row stride
#define XBYTES (96*XLD*2)   // 75264
#define NTHR 384

__device__ __forceinline__ float tf32r(float x){
    float r;
    asm("{\n .reg .b32 t;\n cvt.rna.tf32.f32 t, %1;\n mov.b32 %0, t;\n}"
        : "=f"(r) : "f"(x));
    return r;
}
__device__ __forceinline__ float gelu_f(float x){
    return 0.5f * x * (1.0f + erff(x * 0.7071067811865476f));
}

// ---------------------------------------------------------------------------
// Weight conversion
// ---------------------------------------------------------------------------
__global__ void cvt_weights(const float* __restrict__ w1, const float* __restrict__ w2,
                            const float* __restrict__ w3, const float* __restrict__ w11,
                            const float* __restrict__ w12, const float* __restrict__ w13,
                            const float* __restrict__ win, const float* __restrict__ wout){
    int i = blockIdx.x * blockDim.x + threadIdx.x;
    if (i < NBTOT){
        float v;
        if      (i < NB2)   v = w1[i - NB1];
        else if (i < NB3)   v = w2[i - NB2];
        else if (i < NB11)  v = w3[i - NB3];
        else if (i < NB12)  v = w11[i - NB11];
        else if (i < NB13)  v = w12[i - NB12];
        else                v = w13[i - NB13];
        g_wb[i] = __float2bfloat16(v);
    }
    if (i < CWTOT){
        float w = (i < CWOUT) ? win[i] : wout[i - CWOUT];
        g_cw[i] = tf32r(w);
    }
}

using FragA = wmma::fragment<wmma::matrix_a,16,16,16,__nv_bfloat16,wmma::row_major>;
using FragB = wmma::fragment<wmma::matrix_b,16,16,16,__nv_bfloat16,wmma::col_major>;
using FragC = wmma::fragment<wmma::accumulator,16,16,16,float>;

// ---------------------------------------------------------------------------
// Accumulator-fragment layout self-calibration: decode (lane,i) -> (row,col)
// by loading a known 16x16 pattern. Packed as bytes: v = row*16+col.
// scratch: warp-private 256 floats, 16B aligned.
// ---------------------------------------------------------------------------
__device__ __forceinline__ void calib_maps(float* scratch, int lane,
                                           unsigned& p0, unsigned& p1){
    for (int i = lane; i < 256; i += 32) scratch[i] = (float)i;
    __syncwarp();
    FragC f;
    wmma::load_matrix_sync(f, scratch, 16, wmma::mem_row_major);
    p0 = 0; p1 = 0;
#pragma unroll
    for (int i = 0; i < 4; i++) p0 |= ((unsigned)(int)f.x[i])     << (8 * i);
#pragma unroll
    for (int i = 0; i < 4; i++) p1 |= ((unsigned)(int)f.x[i + 4]) << (8 * i);
}

// ---------------------------------------------------------------------------
// 12-warp GEMM on 96-row tile: warp (mw 0..2, nw 0..3) computes 32x32 block.
// A: smem bf16 row-major; B: global bf16 W row-major viewed col-major (ldb=K).
// ---------------------------------------------------------------------------
template<int NK>
__device__ __forceinline__ void wg12(const __nv_bfloat16* __restrict__ As, int lda,
                                     const __nv_bfloat16* __restrict__ Bg, int ldb,
                                     FragC (&acc)[2][2], int mw, int nw){
#pragma unroll
    for (int t = 0; t < 2; t++)
#pragma unroll
        for (int u = 0; u < 2; u++) wmma::fill_fragment(acc[t][u], 0.0f);

    const __nv_bfloat16* B0 = Bg + (size_t)(nw * 32) * ldb;
    const __nv_bfloat16* B1 = B0 + (size_t)16 * ldb;
    const __nv_bfloat16* Am = As + (size_t)(mw * 32) * lda;

    FragB bf[2][2];
    wmma::load_matrix_sync(bf[0][0], B0, ldb);
    wmma::load_matrix_sync(bf[0][1], B1, ldb);
#pragma unroll 4
    for (int ks = 0; ks < NK; ks++){
        if (ks + 1 < NK){
            wmma::load_matrix_sync(bf[(ks + 1) & 1][0], B0 + (ks + 1) * 16, ldb);
            wmma::load_matrix_sync(bf[(ks + 1) & 1][1], B1 + (ks + 1) * 16, ldb);
        }
#pragma unroll
        for (int t = 0; t < 2; t++){
            FragA af;
            wmma::load_matrix_sync(af, Am + t * 16 * lda + ks * 16, lda);
            wmma::mma_sync(acc[t][0], af, bf[ks & 1][0], acc[t][0]);
            wmma::mma_sync(acc[t][1], af, bf[ks & 1][1], acc[t][1]);
        }
    }
}

// Fused epilogue: bias + gelu + bf16-convert from registers straight to dst.
__device__ __forceinline__ void epi_gelu(FragC (&acc)[2][2], __nv_bfloat16* dst, int ldd,
                                         const float* sbias, int mw, int nw,
                                         unsigned p0, unsigned p1){
#pragma unroll
    for (int t = 0; t < 2; t++)
#pragma unroll
        for (int u = 0; u < 2; u++){
            int rb = mw * 32 + t * 16, cb = nw * 32 + u * 16;
#pragma unroll
            for (int i = 0; i < 8; i++){
                unsigned v = ((i < 4 ? p0 : p1) >> (8 * (i & 3))) & 255u;
                int r = rb + (int)(v >> 4);
                int c = cb + (int)(v & 15u);
                dst[r * ldd + c] = __float2bfloat16(gelu_f(acc[t][u].x[i] + sbias[c]));
            }
        }
}

__device__ __forceinline__ void store_acc2(FragC (&acc)[2][2], float* F, int mw, int nw){
#pragma unroll
    for (int t = 0; t < 2; t++)
#pragma unroll
        for (int u = 0; u < 2; u++)
            wmma::store_matrix_sync(F + (size_t)(mw * 32 + t * 16) * FLD + nw * 32 + u * 16,
                                    acc[t][u], FLD, wmma::mem_row_major);
}

// ---------------------------------------------------------------------------
// Kernel 1: node message MLP + masked k-sum + residual + LN1 -> g_v1
// 2 nodes per CTA (96 rows), 384 threads / 12 warps.
// ---------------------------------------------------------------------------
__global__ __launch_bounds__(NTHR, 2) void node_kernel(
    const float* __restrict__ hV, const float* __restrict__ hE,
    const int* __restrict__ Eidx, const float* __restrict__ mAtt,
    const float* __restrict__ b1, const float* __restrict__ b2v, const float* __restrict__ b3,
    const float* __restrict__ g1, const float* __restrict__ lb1){
    extern __shared__ __align__(128) char smc[];
    __nv_bfloat16* bfX = (__nv_bfloat16*)smc;
    float*         F   = (float*)smc;
    __nv_bfloat16* bfH = (__nv_bfloat16*)(smc + XBYTES);
    __shared__ float smask[96];
    __shared__ float sb_a[128], sb_b[128];
    __shared__ float red[2][8];
    __shared__ float bc[2][2];

    int nA  = blockIdx.x * 2;
    int tid = threadIdx.x, wid = tid >> 5, lane = tid & 31;
    int mw = wid >> 2, nw = wid & 3;

    // fragment-layout calibration (warp-private scratch inside bfH region)
    unsigned p0, p1;
    calib_maps((float*)bfH + wid * 256, lane, p0, p1);

    if (tid < 96)  smask[tid] = mAtt[(size_t)nA * KK + tid];
    if (tid >= 96 && tid < 224)  sb_a[tid - 96] = b1[tid - 96];
    if (tid >= 224 && tid < 352) sb_b[tid - 224] = b2v[tid - 224];

    // build concat tile [96 x 384] in bf16
    for (int i = tid; i < 96 * 384; i += NTHR){
        int r = i / 384, c = i - r * 384;
        int half = (r >= 48);
        int node = nA + half;
        int rr = r - half * 48;
        float v;
        if      (c < 128) v = hV[(size_t)node * HH + c];
        else if (c < 256) v = hE[((size_t)node * KK + rr) * HH + (c - 128)];
        else{
            int baseb = node & ~(LL - 1);
            int idx = Eidx[(size_t)node * KK + rr];
            v = hV[((size_t)(baseb + idx)) * HH + (c - 256)];
        }
        bfX[(size_t)r * XLD + c] = __float2bfloat16(v);
    }
    __syncthreads();

    FragC acc[2][2];
    // layer 1: reads bfX, fused epilogue writes bfH (disjoint region)
    wg12<24>(bfX, XLD, g_wb + NB1, 384, acc, mw, nw);
    epi_gelu(acc, bfH, HLD, sb_a, mw, nw, p0, p1);
    __syncthreads();
    // layer 2: reads bfH, writes bfH (sync separates read/write phases)
    wg12<8>(bfH, HLD, g_wb + NB2, 128, acc, mw, nw);
    __syncthreads();
    epi_gelu(acc, bfH, HLD, sb_b, mw, nw, p0, p1);
    __syncthreads();
    // layer 3: reads bfH, stage f32 into F (aliased bfX region, dead)
    wg12<8>(bfH, HLD, g_wb + NB3, 128, acc, mw, nw);
    store_acc2(acc, F, mw, nw);
    __syncthreads();

    // masked k-sum /30 + residual, per-node LN over 128 channels (first 256 thr)
    if (tid < 256){
        int j = tid >> 7, col = tid & 127;
        int node = nA + j;
        float b3c = b3[col], s = 0.f;
#pragma unroll 8
        for (int r = 0; r < KK; r++)
            s += smask[j * KK + r] * (F[(j * KK + r) * FLD + col] + b3c);
        float t = hV[(size_t)node * HH + col] + s * (1.0f / 30.0f);

        float s1 = t, s2 = t * t;
#pragma unroll
        for (int o = 16; o; o >>= 1){
            s1 += __shfl_xor_sync(0xffffffffu, s1, o);
            s2 += __shfl_xor_sync(0xffffffffu, s2, o);
        }
        if (lane == 0){ red[0][wid] = s1; red[1][wid] = s2; }
        __syncthreads();
        if (tid < 2){
            float a = 0.f, q = 0.f;
            for (int i = 0; i < 4; i++){ a += red[0][tid * 4 + i]; q += red[1][tid * 4 + i]; }
            float m = a * (1.f / 128.f);
            bc[tid][0] = m;
            bc[tid][1] = rsqrtf(q * (1.f / 128.f) - m * m + 1e-5f);
        }
        __syncthreads();
        g_v1[(size_t)node * HH + col] = (t - bc[j][0]) * bc[j][1] * g1[col] + lb1[col];
    } else {
        __syncthreads();
        __syncthreads();
    }
}

// ---------------------------------------------------------------------------
// Kernel 2: position-wise FFN + residual + LN2 + mask_V (tf32, unchanged)
// ---------------------------------------------------------------------------
__global__ __launch_bounds__(256, 2) void ffn_kernel(
    const float* __restrict__ maskV,
    const float* __restrict__ winb, const float* __restrict__ woutb,
    const float* __restrict__ g2, const float* __restrict__ lb2,
    float* __restrict__ outV){
    extern __shared__ __align__(128) float sm[];
    float* Xv = sm;              // 64 x 136
    float* Hc = sm + 64 * 136;   // 64 x 136
    int tid = threadIdx.x, wid = tid >> 5, lane = tid & 31;
    int node0 = blockIdx.x * 64;

    for (int i = tid; i < 64 * 128; i += 256){
        int r = i >> 7, c = i & 127;
        Xv[r * 136 + c] = tf32r(g_v1[(size_t)(node0 + r) * HH + c]);
    }
    __syncthreads();

    int mt = wid & 3, ng = wid >> 2;
    int m0 = mt * 16;
    wmma::fragment<wmma::accumulator,16,16,8,float> accO[4];
#pragma unroll
    for (int j = 0; j < 4; j++) wmma::fill_fragment(accO[j], 0.0f);

    for (int ch = 0; ch < 4; ch++){
#pragma unroll
        for (int j = 0; j < 4; j++){
            int n0 = (ng * 4 + j) * 16;
            wmma::fragment<wmma::accumulator,16,16,8,float> c;
            wmma::fill_fragment(c, 0.0f);
            const float* Bp = g_cw + CWIN + ch * 128 * 128 + n0 * 128;
            wmma::fragment<wmma::matrix_b,16,16,8,wmma::precision::tf32,wmma::col_major> bf[2];
            wmma::load_matrix_sync(bf[0], Bp, 128);
#pragma unroll
            for (int ks = 0; ks < 16; ks++){
                if (ks + 1 < 16) wmma::load_matrix_sync(bf[(ks + 1) & 1], Bp + (ks + 1) * 8, 128);
                wmma::fragment<wmma::matrix_a,16,16,8,wmma::precision::tf32,wmma::row_major> af;
                wmma::load_matrix_sync(af, Xv + m0 * 136 + ks * 8, 136);
                wmma::mma_sync(c, af, bf[ks & 1], c);
            }
            wmma::store_matrix_sync(Hc + m0 * 136 + n0, c, 136, wmma::mem_row_major);
        }
        __syncthreads();
        for (int i = tid; i < 64 * 128; i += 256){
            int r = i >> 7, c = i & 127;
            Hc[r * 136 + c] = tf32r(gelu_f(Hc[r * 136 + c] + winb[ch * 128 + c]));
        }
        __syncthreads();
#pragma unroll
        for (int j = 0; j < 4; j++){
            int n0g = (ng * 4 + j) * 16;
            const float* Bp = g_cw + CWOUT + n0g * 512 + ch * 128;
            wmma::fragment<wmma::matrix_b,16,16,8,wmma::precision::tf32,wmma::col_major> bf[2];
            wmma::load_matrix_sync(bf[0], Bp, 512);
#pragma unroll
            for (int ks = 0; ks < 16; ks++){
                if (ks + 1 < 16) wmma::load_matrix_sync(bf[(ks + 1) & 1], Bp + (ks + 1) * 8, 512);
                wmma::fragment<wmma::matrix_a,16,16,8,wmma::precision::tf32,wmma::row_major> af;
                wmma::load_matrix_sync(af, Hc + m0 * 136 + ks * 8, 136);
                wmma::mma_sync(accO[j], af, bf[ks & 1], accO[j]);
            }
        }
        __syncthreads();
    }
#pragma unroll
    for (int j = 0; j < 4; j++)
        wmma::store_matrix_sync(Xv + m0 * 136 + (ng * 4 + j) * 16, accO[j], 136, wmma::mem_row_major);
    __syncthreads();

    for (int rr = 0; rr < 8; rr++){
        int r = wid * 8 + rr;
        int node = node0 + r;
        float mv = maskV[node];
        float v[4]; float s1 = 0.f, s2 = 0.f;
#pragma unroll
        for (int j = 0; j < 4; j++){
            int c = lane + j * 32;
            float x = g_v1[(size_t)node * HH + c] + Xv[r * 136 + c] + woutb[c];
            v[j] = x; s1 += x; s2 += x * x;
        }
#pragma unroll
        for (int o = 16; o; o >>= 1){
            s1 += __shfl_xor_sync(0xffffffffu, s1, o);
            s2 += __shfl_xor_sync(0xffffffffu, s2, o);
        }
        float m  = s1 * (1.f / 128.f);
        float rs = rsqrtf(s2 * (1.f / 128.f) - m * m + 1e-5f);
#pragma unroll
        for (int j = 0; j < 4; j++){
            int c = lane + j * 32;
            float o = mv * ((v[j] - m) * rs * g2[c] + lb2[c]);
            outV[(size_t)node * HH + c] = o;
            g_v2[(size_t)node * HH + c] = o;
        }
    }
}

// ---------------------------------------------------------------------------
// Kernel 3: edge message MLP + residual + LN3 -> out h_E
// ---------------------------------------------------------------------------
__global__ __launch_bounds__(NTHR, 2) void edge_kernel(
    const float* __restrict__ hE, const int* __restrict__ Eidx,
    const float* __restrict__ b11, const float* __restrict__ b12, const float* __restrict__ b13,
    const float* __restrict__ g3, const float* __restrict__ lb3,
    float* __restrict__ outE){
    extern __shared__ __align__(128) char smc[];
    __nv_bfloat16* bfX = (__nv_bfloat16*)smc;
    float*         F   = (float*)smc;
    __nv_bfloat16* bfH = (__nv_bfloat16*)(smc + XBYTES);
    __shared__ float sb_a[128], sb_b[128];

    int nA  = blockIdx.x * 2;
    int tid = threadIdx.x, wid = tid >> 5, lane = tid & 31;
    int mw = wid >> 2, nw = wid & 3;

    unsigned p0, p1;
    calib_maps((float*)bfH + wid * 256, lane, p0, p1);

    if (tid < 128)                sb_a[tid] = b11[tid];
    if (tid >= 128 && tid < 256)  sb_b[tid - 128] = b12[tid - 128];

    for (int i = tid; i < 96 * 384; i += NTHR){
        int r = i / 384, c = i - r * 384;
        int half = (r >= 48);
        int node = nA + half;
        int rr = r - half * 48;
        float v;
        if      (c < 128) v = g_v2[(size_t)node * HH + c];
        else if (c < 256) v = hE[((size_t)node * KK + rr) * HH + (c - 128)];
        else{
            int baseb = node & ~(LL - 1);
            int idx = Eidx[(size_t)node * KK + rr];
            v = g_v2[((size_t)(baseb + idx)) * HH + (c - 256)];
        }
        bfX[(size_t)r * XLD + c] = __float2bfloat16(v);
    }
    __syncthreads();

    FragC acc[2][2];
    wg12<24>(bfX, XLD, g_wb + NB11, 384, acc, mw, nw);
    epi_gelu(acc, bfH, HLD, sb_a, mw, nw, p0, p1);
    __syncthreads();
    wg12<8>(bfH, HLD, g_wb + NB12, 128, acc, mw, nw);
    __syncthreads();
    epi_gelu(acc, bfH, HLD, sb_b, mw, nw, p0, p1);
    __syncthreads();
    wg12<8>(bfH, HLD, g_wb + NB13, 128, acc, mw, nw);
    store_acc2(acc, F, mw, nw);
    __syncthreads();

    // per-row residual + LN3: 12 warps x 8 rows
    for (int rr = 0; rr < 8; rr++){
        int r = wid * 8 + rr;
        int half = (r >= 48);
        int node = nA + half;
        int er = r - half * 48;
        const float* her = hE + ((size_t)node * KK + er) * HH;
        float v[4]; float s1 = 0.f, s2 = 0.f;
#pragma unroll
        for (int j = 0; j < 4; j++){
            int c = lane + j * 32;
            float x = her[c] + F[r * FLD + c] + b13[c];
            v[j] = x; s1 += x; s2 += x * x;
        }
#pragma unroll
        for (int o = 16; o; o >>= 1){
            s1 += __shfl_xor_sync(0xffffffffu, s1, o);
            s2 += __shfl_xor_sync(0xffffffffu, s2, o);
        }
        float m  = s1 * (1.f / 128.f);
        float rs = rsqrtf(s2 * (1.f / 128.f) - m * m + 1e-5f);
#pragma unroll
        for (int j = 0; j < 4; j++){
            int c = lane + j * 32;
            outE[((size_t)node * KK + er) * HH + c] = (v[j] - m) * rs * g3[c] + lb3[c];
        }
    }
}

// ---------------------------------------------------------------------------
extern "C" void kernel_launch(void* const* d_in, const int* in_sizes, int n_in,
                              void* d_out, int out_size){
    (void)in_sizes; (void)n_in; (void)out_size;
    const float* hV    = (const float*)d_in[0];
    const float* hE    = (const float*)d_in[1];
    const int*   Eidx  = (const int*)  d_in[2];
    const float* maskV = (const float*)d_in[3];
    const float* mAtt  = (const float*)d_in[4];
    const float* W1  = (const float*)d_in[5];  const float* b1  = (const float*)d_in[6];
    const float* W2  = (const float*)d_in[7];  const float* b2  = (const float*)d_in[8];
    const float* W3  = (const float*)d_in[9];  const float* b3  = (const float*)d_in[10];
    const float* W11 = (const float*)d_in[11]; const float* b11 = (const float*)d_in[12];
    const float* W12 = (const float*)d_in[13]; const float* b12 = (const float*)d_in[14];
    const float* W13 = (const float*)d_in[15]; const float* b13 = (const float*)d_in[16];
    const float* Win = (const float*)d_in[17]; const float* Winb = (const float*)d_in[18];
    const float* Wout= (const float*)d_in[19]; const float* Woutb= (const float*)d_in[20];
    const float* g1  = (const float*)d_in[21]; const float* lb1 = (const float*)d_in[22];
    const float* g2  = (const float*)d_in[23]; const float* lb2 = (const float*)d_in[24];
    const float* g3  = (const float*)d_in[25]; const float* lb3 = (const float*)d_in[26];

    float* outV = (float*)d_out;
    float* outE = outV + (size_t)BB * LL * HH;

    const int smem1 = XBYTES + 96 * HLD * 2;       // 101376 B
    const int smem2 = 2 * 64 * 136 * 4;            // 69632 B
    cudaFuncSetAttribute(node_kernel, cudaFuncAttributeMaxDynamicSharedMemorySize, smem1);
    cudaFuncSetAttribute(edge_kernel, cudaFuncAttributeMaxDynamicSharedMemorySize, smem1);
    cudaFuncSetAttribute(ffn_kernel,  cudaFuncAttributeMaxDynamicSharedMemorySize, smem2);

    cvt_weights<<<(NBTOT + 255) / 256, 256>>>(W1, W2, W3, W11, W12, W13, Win, Wout);
    node_kernel<<<BB * LL / 2, NTHR, smem1>>>(hV, hE, Eidx, mAtt, b1, b2, b3, g1, lb1);
    ffn_kernel<<<BB * LL / 64, 256, smem2>>>(maskV, Winb, Woutb, g2, lb2, outV);
    edge_kernel<<<BB * LL / 2, NTHR, smem1>>>(hE, Eidx, b11, b12, b13, g3, lb3, outE);
}

// round 15
// speedup vs baseline: 1.5934x; 1.5934x over previous
#include <cuda_runtime.h>
#include <cuda_bf16.h>
#include <mma.h>
#include <math.h>

using namespace nvcuda;

#define BB 4
#define LL 2048
#define KK 48
#define HH 128
#define NPAIR (BB*LL/2)
#define PGRID 296

// bf16 weights (node + edge MLPs) in global scratch
#define NB1   0
#define NB2   49152
#define NB3   65536
#define NB11  81920
#define NB12  131072
#define NB13  147456
#define NBTOT 163840
// tf32-f32 weights (FFN)
#define CWIN  0
#define CWOUT 65536
#define CWTOT 131072

__device__ __nv_bfloat16 g_wb[NBTOT];
__device__ float g_cw[CWTOT];
__device__ float g_v1[BB*LL*HH];   // h_V after node update + LN1
__device__ float g_v2[BB*LL*HH];   // h_V after FFN + LN2 + mask

// ---- persistent-CTA smem layout (bytes) ----
#define XLD2 264              // X tile stride (bf16 elems), K=256 +8 pad
#define FLD  132              // f32 staging stride (aliases X: 264*2 == 132*4)
#define HLD  136              // H tile / W2 / W3 stride (bf16)
#define OW1  0                // W1[e|nb] as B col-major: 128 cols x 264  = 67584 B
#define OW2  67584            // 128 x 136 bf16 = 34816 B
#define OW3  102400           // 34816 B
#define OX   137216           // 96 x 264 bf16 = 50688 B (aliases F 96x132 f32)
#define OH   187904           // 96 x 136 bf16 = 26112 B
#define OPV  214016           // 256 f32 = 1024 B
#define SMTOT 215040
#define NTHR 512

__device__ __forceinline__ float tf32r(float x){
    float r;
    asm("{\n .reg .b32 t;\n cvt.rna.tf32.f32 t, %1;\n mov.b32 %0, t;\n}"
        : "=f"(r) : "f"(x));
    return r;
}
__device__ __forceinline__ float gelu_f(float x){
    return 0.5f * x * (1.0f + erff(x * 0.7071067811865476f));
}

// ---------------------------------------------------------------------------
// Weight conversion
// ---------------------------------------------------------------------------
__global__ void cvt_weights(const float* __restrict__ w1, const float* __restrict__ w2,
                            const float* __restrict__ w3, const float* __restrict__ w11,
                            const float* __restrict__ w12, const float* __restrict__ w13,
                            const float* __restrict__ win, const float* __restrict__ wout){
    int i = blockIdx.x * blockDim.x + threadIdx.x;
    if (i < NBTOT){
        float v;
        if      (i < NB2)   v = w1[i - NB1];
        else if (i < NB3)   v = w2[i - NB2];
        else if (i < NB11)  v = w3[i - NB3];
        else if (i < NB12)  v = w11[i - NB11];
        else if (i < NB13)  v = w12[i - NB12];
        else                v = w13[i - NB13];
        g_wb[i] = __float2bfloat16(v);
    }
    if (i < CWTOT){
        float w = (i < CWOUT) ? win[i] : wout[i - CWOUT];
        g_cw[i] = tf32r(w);
    }
}

using FragA = wmma::fragment<wmma::matrix_a,16,16,16,__nv_bfloat16,wmma::row_major>;
using FragB = wmma::fragment<wmma::matrix_b,16,16,16,__nv_bfloat16,wmma::col_major>;
using FragC = wmma::fragment<wmma::accumulator,16,16,16,float>;

// Accumulator (lane,i)->(row,col) self-calibration (verified in prior round).
__device__ __forceinline__ void calib_maps(float* scratch, int lane,
                                           unsigned& p0, unsigned& p1){
    for (int i = lane; i < 256; i += 32) scratch[i] = (float)i;
    __syncwarp();
    FragC f;
    wmma::load_matrix_sync(f, scratch, 16, wmma::mem_row_major);
    p0 = 0; p1 = 0;
#pragma unroll
    for (int i = 0; i < 4; i++) p0 |= ((unsigned)(int)f.x[i])     << (8 * i);
#pragma unroll
    for (int i = 0; i < 4; i++) p1 |= ((unsigned)(int)f.x[i + 4]) << (8 * i);
}

// 12-warp GEMM on 96-row tile: warp (mw 0..2, nw 0..3) -> 32x32 block.
// A and B both in SMEM now.
template<int NK>
__device__ __forceinline__ void wg12(const __nv_bfloat16* As, int lda,
                                     const __nv_bfloat16* Bs, int ldb,
                                     FragC (&acc)[2][2], int mw, int nw){
#pragma unroll
    for (int t = 0; t < 2; t++)
#pragma unroll
        for (int u = 0; u < 2; u++) wmma::fill_fragment(acc[t][u], 0.0f);

    const __nv_bfloat16* B0 = Bs + (size_t)(nw * 32) * ldb;
    const __nv_bfloat16* B1 = B0 + (size_t)16 * ldb;
    const __nv_bfloat16* Am = As + (size_t)(mw * 32) * lda;

#pragma unroll 4
    for (int ks = 0; ks < NK; ks++){
        FragB b0, b1;
        wmma::load_matrix_sync(b0, B0 + ks * 16, ldb);
        wmma::load_matrix_sync(b1, B1 + ks * 16, ldb);
#pragma unroll
        for (int t = 0; t < 2; t++){
            FragA af;
            wmma::load_matrix_sync(af, Am + t * 16 * lda + ks * 16, lda);
            wmma::mma_sync(acc[t][0], af, b0, acc[t][0]);
            wmma::mma_sync(acc[t][1], af, b1, acc[t][1]);
        }
    }
}

// Fused epilogue: (+pv) + bias + gelu + bf16, registers -> smem dst.
__device__ __forceinline__ void epi_gelu(FragC (&acc)[2][2], __nv_bfloat16* dst, int ldd,
                                         const float* sbias, const float* pv,
                                         int mw, int nw, unsigned p0, unsigned p1){
#pragma unroll
    for (int t = 0; t < 2; t++)
#pragma unroll
        for (int u = 0; u < 2; u++){
            int rb = mw * 32 + t * 16, cb = nw * 32 + u * 16;
#pragma unroll
            for (int i = 0; i < 8; i++){
                unsigned v = ((i < 4 ? p0 : p1) >> (8 * (i & 3))) & 255u;
                int r = rb + (int)(v >> 4);
                int c = cb + (int)(v & 15u);
                float x = acc[t][u].x[i] + sbias[c];
                if (pv) x += pv[(r >= 48) * 128 + c];
                dst[r * ldd + c] = __float2bfloat16(gelu_f(x));
            }
        }
}

__device__ __forceinline__ void store_acc2(FragC (&acc)[2][2], float* F, int mw, int nw){
#pragma unroll
    for (int t = 0; t < 2; t++)
#pragma unroll
        for (int u = 0; u < 2; u++)
            wmma::store_matrix_sync(F + (size_t)(mw * 32 + t * 16) * FLD + nw * 32 + u * 16,
                                    acc[t][u], FLD, wmma::mem_row_major);
}

// Stage the three MLP weight matrices into smem (B col-major, padded strides).
__device__ __forceinline__ void stage_weights(char* smc, int woff1, int woff2, int woff3, int tid){
    for (int idx = tid; idx < 128 * 32; idx += NTHR){
        int o = idx >> 5, q = idx & 31;   // cols 128..383 of W row o
        *(uint4*)(smc + OW1 + o * (XLD2 * 2) + q * 16) =
            *(const uint4*)((const char*)(g_wb + woff1 + o * 384 + 128) + q * 16);
    }
    for (int idx = tid; idx < 128 * 16; idx += NTHR){
        int o = idx >> 4, q = idx & 15;
        *(uint4*)(smc + OW2 + o * (HLD * 2) + q * 16) =
            *(const uint4*)((const char*)(g_wb + woff2 + o * 128) + q * 16);
        *(uint4*)(smc + OW3 + o * (HLD * 2) + q * 16) =
            *(const uint4*)((const char*)(g_wb + woff3 + o * 128) + q * 16);
    }
}

// ---------------------------------------------------------------------------
// Kernel 1: node message MLP + masked k-sum + residual + LN1 -> g_v1
// Persistent: each CTA stages weights once, loops over node-pairs.
// ---------------------------------------------------------------------------
__global__ __launch_bounds__(NTHR, 1) void node_kernel(
    const float* __restrict__ hV, const float* __restrict__ hE,
    const int* __restrict__ Eidx, const float* __restrict__ mAtt,
    const float* __restrict__ W1f,
    const float* __restrict__ b1, const float* __restrict__ b2v, const float* __restrict__ b3,
    const float* __restrict__ g1, const float* __restrict__ lb1){
    extern __shared__ __align__(128) char smc[];
    __nv_bfloat16* sW1 = (__nv_bfloat16*)(smc + OW1);
    __nv_bfloat16* sW2 = (__nv_bfloat16*)(smc + OW2);
    __nv_bfloat16* sW3 = (__nv_bfloat16*)(smc + OW3);
    __nv_bfloat16* bfX = (__nv_bfloat16*)(smc + OX);
    float*         F   = (float*)(smc + OX);
    __nv_bfloat16* bfH = (__nv_bfloat16*)(smc + OH);
    float*         pv  = (float*)(smc + OPV);
    __shared__ float smask[96];
    __shared__ float sb_a[128], sb_b[128];
    __shared__ float red[2][8];
    __shared__ float bc[2][2];

    int tid = threadIdx.x, wid = tid >> 5, lane = tid & 31;
    int mw = wid >> 2, nw = wid & 3;           // compute warps: wid < 12

    unsigned p0, p1;
    calib_maps((float*)bfH + wid * 256, lane, p0, p1);

    stage_weights(smc, NB1, NB2, NB3, tid);
    if (tid < 128)                sb_a[tid] = b1[tid];
    else if (tid < 256)           sb_b[tid - 128] = b2v[tid - 128];

    for (int pair = blockIdx.x; pair < NPAIR; pair += gridDim.x){
        int nA = pair * 2;
        __syncthreads();   // prev iter done reading F / first iter: staging done

        // gather [96 x 256] = [hE | hNb] in bf16
        for (int i = tid; i < 96 * 256; i += NTHR){
            int r = i >> 8, c = i & 255;
            int half = (r >= 48);
            int node = nA + half;
            int rr = r - half * 48;
            float v;
            if (c < 128) v = hE[((size_t)node * KK + rr) * HH + c];
            else{
                int baseb = node & ~(LL - 1);
                int idx = Eidx[(size_t)node * KK + rr];
                v = hV[((size_t)(baseb + idx)) * HH + (c - 128)];
            }
            bfX[(size_t)r * XLD2 + c] = __float2bfloat16(v);
        }
        if (tid < 96) smask[tid] = mAtt[(size_t)nA * KK + tid];
        __syncthreads();

        FragC acc[2][2];
        if (wid < 12){
            wg12<16>(bfX, XLD2, sW1, XLD2, acc, mw, nw);
        } else {
            // pv[j*128+o] = W1[:, 0:128] @ v_j  in f32 (exact path)
            int t = (wid - 12) * 32 + lane;   // 0..127
            const float4* Wr = (const float4*)(W1f + (size_t)t * 384);
            const float4* v0 = (const float4*)(hV + (size_t)nA * HH);
            const float4* v1 = (const float4*)(hV + (size_t)(nA + 1) * HH);
            float d0 = 0.f, d1 = 0.f;
#pragma unroll 8
            for (int q = 0; q < 32; q++){
                float4 w = Wr[q], a = v0[q], b = v1[q];
                d0 += w.x*a.x + w.y*a.y + w.z*a.z + w.w*a.w;
                d1 += w.x*b.x + w.y*b.y + w.z*b.z + w.w*b.w;
            }
            pv[t] = d0; pv[128 + t] = d1;
        }
        __syncthreads();
        if (wid < 12) epi_gelu(acc, bfH, HLD, sb_a, pv, mw, nw, p0, p1);
        __syncthreads();
        if (wid < 12) wg12<8>(bfH, HLD, sW2, HLD, acc, mw, nw);
        __syncthreads();
        if (wid < 12) epi_gelu(acc, bfH, HLD, sb_b, nullptr, mw, nw, p0, p1);
        __syncthreads();
        if (wid < 12){
            wg12<8>(bfH, HLD, sW3, HLD, acc, mw, nw);
            store_acc2(acc, F, mw, nw);
        }
        __syncthreads();

        // masked k-sum /30 + residual + per-node LN (first 256 threads)
        float t = 0.f; int j = 0, col = 0, node = nA;
        if (tid < 256){
            j = tid >> 7; col = tid & 127; node = nA + j;
            float b3c = b3[col], s = 0.f;
#pragma unroll 8
            for (int r = 0; r < KK; r++)
                s += smask[j * KK + r] * (F[(j * KK + r) * FLD + col] + b3c);
            t = hV[(size_t)node * HH + col] + s * (1.0f / 30.0f);
            float s1 = t, s2 = t * t;
#pragma unroll
            for (int o = 16; o; o >>= 1){
                s1 += __shfl_xor_sync(0xffffffffu, s1, o);
                s2 += __shfl_xor_sync(0xffffffffu, s2, o);
            }
            if (lane == 0){ red[0][wid] = s1; red[1][wid] = s2; }
        }
        __syncthreads();
        if (tid < 2){
            float a = 0.f, q = 0.f;
            for (int i = 0; i < 4; i++){ a += red[0][tid * 4 + i]; q += red[1][tid * 4 + i]; }
            float m = a * (1.f / 128.f);
            bc[tid][0] = m;
            bc[tid][1] = rsqrtf(q * (1.f / 128.f) - m * m + 1e-5f);
        }
        __syncthreads();
        if (tid < 256)
            g_v1[(size_t)node * HH + col] = (t - bc[j][0]) * bc[j][1] * g1[col] + lb1[col];
    }
}

// ---------------------------------------------------------------------------
// Kernel 2: position-wise FFN + residual + LN2 + mask_V (tf32, unchanged)
// ---------------------------------------------------------------------------
__global__ __launch_bounds__(256, 2) void ffn_kernel(
    const float* __restrict__ maskV,
    const float* __restrict__ winb, const float* __restrict__ woutb,
    const float* __restrict__ g2, const float* __restrict__ lb2,
    float* __restrict__ outV){
    extern __shared__ __align__(128) float sm[];
    float* Xv = sm;              // 64 x 136
    float* Hc = sm + 64 * 136;   // 64 x 136
    int tid = threadIdx.x, wid = tid >> 5, lane = tid & 31;
    int node0 = blockIdx.x * 64;

    for (int i = tid; i < 64 * 128; i += 256){
        int r = i >> 7, c = i & 127;
        Xv[r * 136 + c] = tf32r(g_v1[(size_t)(node0 + r) * HH + c]);
    }
    __syncthreads();

    int mt = wid & 3, ng = wid >> 2;
    int m0 = mt * 16;
    wmma::fragment<wmma::accumulator,16,16,8,float> accO[4];
#pragma unroll
    for (int j = 0; j < 4; j++) wmma::fill_fragment(accO[j], 0.0f);

    for (int ch = 0; ch < 4; ch++){
#pragma unroll
        for (int j = 0; j < 4; j++){
            int n0 = (ng * 4 + j) * 16;
            wmma::fragment<wmma::accumulator,16,16,8,float> c;
            wmma::fill_fragment(c, 0.0f);
            const float* Bp = g_cw + CWIN + ch * 128 * 128 + n0 * 128;
            wmma::fragment<wmma::matrix_b,16,16,8,wmma::precision::tf32,wmma::col_major> bf[2];
            wmma::load_matrix_sync(bf[0], Bp, 128);
#pragma unroll
            for (int ks = 0; ks < 16; ks++){
                if (ks + 1 < 16) wmma::load_matrix_sync(bf[(ks + 1) & 1], Bp + (ks + 1) * 8, 128);
                wmma::fragment<wmma::matrix_a,16,16,8,wmma::precision::tf32,wmma::row_major> af;
                wmma::load_matrix_sync(af, Xv + m0 * 136 + ks * 8, 136);
                wmma::mma_sync(c, af, bf[ks & 1], c);
            }
            wmma::store_matrix_sync(Hc + m0 * 136 + n0, c, 136, wmma::mem_row_major);
        }
        __syncthreads();
        for (int i = tid; i < 64 * 128; i += 256){
            int r = i >> 7, c = i & 127;
            Hc[r * 136 + c] = tf32r(gelu_f(Hc[r * 136 + c] + winb[ch * 128 + c]));
        }
        __syncthreads();
#pragma unroll
        for (int j = 0; j < 4; j++){
            int n0g = (ng * 4 + j) * 16;
            const float* Bp = g_cw + CWOUT + n0g * 512 + ch * 128;
            wmma::fragment<wmma::matrix_b,16,16,8,wmma::precision::tf32,wmma::col_major> bf[2];
            wmma::load_matrix_sync(bf[0], Bp, 512);
#pragma unroll
            for (int ks = 0; ks < 16; ks++){
                if (ks + 1 < 16) wmma::load_matrix_sync(bf[(ks + 1) & 1], Bp + (ks + 1) * 8, 512);
                wmma::fragment<wmma::matrix_a,16,16,8,wmma::precision::tf32,wmma::row_major> af;
                wmma::load_matrix_sync(af, Hc + m0 * 136 + ks * 8, 136);
                wmma::mma_sync(accO[j], af, bf[ks & 1], accO[j]);
            }
        }
        __syncthreads();
    }
#pragma unroll
    for (int j = 0; j < 4; j++)
        wmma::store_matrix_sync(Xv + m0 * 136 + (ng * 4 + j) * 16, accO[j], 136, wmma::mem_row_major);
    __syncthreads();

    for (int rr = 0; rr < 8; rr++){
        int r = wid * 8 + rr;
        int node = node0 + r;
        float mv = maskV[node];
        float v[4]; float s1 = 0.f, s2 = 0.f;
#pragma unroll
        for (int j = 0; j < 4; j++){
            int c = lane + j * 32;
            float x = g_v1[(size_t)node * HH + c] + Xv[r * 136 + c] + woutb[c];
            v[j] = x; s1 += x; s2 += x * x;
        }
#pragma unroll
        for (int o = 16; o; o >>= 1){
            s1 += __shfl_xor_sync(0xffffffffu, s1, o);
            s2 += __shfl_xor_sync(0xffffffffu, s2, o);
        }
        float m  = s1 * (1.f / 128.f);
        float rs = rsqrtf(s2 * (1.f / 128.f) - m * m + 1e-5f);
#pragma unroll
        for (int j = 0; j < 4; j++){
            int c = lane + j * 32;
            float o = mv * ((v[j] - m) * rs * g2[c] + lb2[c]);
            outV[(size_t)node * HH + c] = o;
            g_v2[(size_t)node * HH + c] = o;
        }
    }
}

// ---------------------------------------------------------------------------
// Kernel 3: edge message MLP + residual + LN3 -> out h_E (persistent)
// ---------------------------------------------------------------------------
__global__ __launch_bounds__(NTHR, 1) void edge_kernel(
    const float* __restrict__ hE, const int* __restrict__ Eidx,
    const float* __restrict__ W11f,
    const float* __restrict__ b11, const float* __restrict__ b12, const float* __restrict__ b13,
    const float* __restrict__ g3, const float* __restrict__ lb3,
    float* __restrict__ outE){
    extern __shared__ __align__(128) char smc[];
    __nv_bfloat16* sW1 = (__nv_bfloat16*)(smc + OW1);
    __nv_bfloat16* sW2 = (__nv_bfloat16*)(smc + OW2);
    __nv_bfloat16* sW3 = (__nv_bfloat16*)(smc + OW3);
    __nv_bfloat16* bfX = (__nv_bfloat16*)(smc + OX);
    float*         F   = (float*)(smc + OX);
    __nv_bfloat16* bfH = (__nv_bfloat16*)(smc + OH);
    float*         pv  = (float*)(smc + OPV);
    __shared__ float sb_a[128], sb_b[128];

    int tid = threadIdx.x, wid = tid >> 5, lane = tid & 31;
    int mw = wid >> 2, nw = wid & 3;

    unsigned p0, p1;
    calib_maps((float*)bfH + wid * 256, lane, p0, p1);

    stage_weights(smc, NB11, NB12, NB13, tid);
    if (tid < 128)      sb_a[tid] = b11[tid];
    else if (tid < 256) sb_b[tid - 128] = b12[tid - 128];

    for (int pair = blockIdx.x; pair < NPAIR; pair += gridDim.x){
        int nA = pair * 2;
        __syncthreads();

        for (int i = tid; i < 96 * 256; i += NTHR){
            int r = i >> 8, c = i & 255;
            int half = (r >= 48);
            int node = nA + half;
            int rr = r - half * 48;
            float v;
            if (c < 128) v = hE[((size_t)node * KK + rr) * HH + c];
            else{
                int baseb = node & ~(LL - 1);
                int idx = Eidx[(size_t)node * KK + rr];
                v = g_v2[((size_t)(baseb + idx)) * HH + (c - 128)];
            }
            bfX[(size_t)r * XLD2 + c] = __float2bfloat16(v);
        }
        __syncthreads();

        FragC acc[2][2];
        if (wid < 12){
            wg12<16>(bfX, XLD2, sW1, XLD2, acc, mw, nw);
        } else {
            int t = (wid - 12) * 32 + lane;
            const float4* Wr = (const float4*)(W11f + (size_t)t * 384);
            const float4* v0 = (const float4*)(g_v2 + (size_t)nA * HH);
            const float4* v1 = (const float4*)(g_v2 + (size_t)(nA + 1) * HH);
            float d0 = 0.f, d1 = 0.f;
#pragma unroll 8
            for (int q = 0; q < 32; q++){
                float4 w = Wr[q], a = v0[q], b = v1[q];
                d0 += w.x*a.x + w.y*a.y + w.z*a.z + w.w*a.w;
                d1 += w.x*b.x + w.y*b.y + w.z*b.z + w.w*b.w;
            }
            pv[t] = d0; pv[128 + t] = d1;
        }
        __syncthreads();
        if (wid < 12) epi_gelu(acc, bfH, HLD, sb_a, pv, mw, nw, p0, p1);
        __syncthreads();
        if (wid < 12) wg12<8>(bfH, HLD, sW2, HLD, acc, mw, nw);
        __syncthreads();
        if (wid < 12) epi_gelu(acc, bfH, HLD, sb_b, nullptr, mw, nw, p0, p1);
        __syncthreads();
        if (wid < 12){
            wg12<8>(bfH, HLD, sW3, HLD, acc, mw, nw);
            store_acc2(acc, F, mw, nw);
        }
        __syncthreads();

        // per-row residual + LN3: 16 warps x 6 rows
        for (int rr = 0; rr < 6; rr++){
            int r = wid * 6 + rr;
            int half = (r >= 48);
            int node = nA + half;
            int er = r - half * 48;
            const float* her = hE + ((size_t)node * KK + er) * HH;
            float v[4]; float s1 = 0.f, s2 = 0.f;
#pragma unroll
            for (int j = 0; j < 4; j++){
                int c = lane + j * 32;
                float x = her[c] + F[r * FLD + c] + b13[c];
                v[j] = x; s1 += x; s2 += x * x;
            }
#pragma unroll
            for (int o = 16; o; o >>= 1){
                s1 += __shfl_xor_sync(0xffffffffu, s1, o);
                s2 += __shfl_xor_sync(0xffffffffu, s2, o);
            }
            float m  = s1 * (1.f / 128.f);
            float rs = rsqrtf(s2 * (1.f / 128.f) - m * m + 1e-5f);
#pragma unroll
            for (int j = 0; j < 4; j++){
                int c = lane + j * 32;
                outE[((size_t)node * KK + er) * HH + c] = (v[j] - m) * rs * g3[c] + lb3[c];
            }
        }
    }
}

// ---------------------------------------------------------------------------
extern "C" void kernel_launch(void* const* d_in, const int* in_sizes, int n_in,
                              void* d_out, int out_size){
    (void)in_sizes; (void)n_in; (void)out_size;
    const float* hV    = (const float*)d_in[0];
    const float* hE    = (const float*)d_in[1];
    const int*   Eidx  = (const int*)  d_in[2];
    const float* maskV = (const float*)d_in[3];
    const float* mAtt  = (const float*)d_in[4];
    const float* W1  = (const float*)d_in[5];  const float* b1  = (const float*)d_in[6];
    const float* W2  = (const float*)d_in[7];  const float* b2  = (const float*)d_in[8];
    const float* W3  = (const float*)d_in[9];  const float* b3  = (const float*)d_in[10];
    const float* W11 = (const float*)d_in[11]; const float* b11 = (const float*)d_in[12];
    const float* W12 = (const float*)d_in[13]; const float* b12 = (const float*)d_in[14];
    const float* W13 = (const float*)d_in[15]; const float* b13 = (const float*)d_in[16];
    const float* Win = (const float*)d_in[17]; const float* Winb = (const float*)d_in[18];
    const float* Wout= (const float*)d_in[19]; const float* Woutb= (const float*)d_in[20];
    const float* g1  = (const float*)d_in[21]; const float* lb1 = (const float*)d_in[22];
    const float* g2  = (const float*)d_in[23]; const float* lb2 = (const float*)d_in[24];
    const float* g3  = (const float*)d_in[25]; const float* lb3 = (const float*)d_in[26];

    float* outV = (float*)d_out;
    float* outE = outV + (size_t)BB * LL * HH;

    const int smem2 = 2 * 64 * 136 * 4;            // 69632 B
    cudaFuncSetAttribute(node_kernel, cudaFuncAttributeMaxDynamicSharedMemorySize, SMTOT);
    cudaFuncSetAttribute(edge_kernel, cudaFuncAttributeMaxDynamicSharedMemorySize, SMTOT);
    cudaFuncSetAttribute(ffn_kernel,  cudaFuncAttributeMaxDynamicSharedMemorySize, smem2);

    cvt_weights<<<(NBTOT + 255) / 256, 256>>>(W1, W2, W3, W11, W12, W13, Win, Wout);
    node_kernel<<<PGRID, NTHR, SMTOT>>>(hV, hE, Eidx, mAtt, W1, b1, b2, b3, g1, lb1);
    ffn_kernel<<<BB * LL / 64, 256, smem2>>>(maskV, Winb, Woutb, g2, lb2, outV);
    edge_kernel<<<PGRID, NTHR, SMTOT>>>(hE, Eidx, W11, b11, b12, b13, g3, lb3, outE);
}

// round 16
// speedup vs baseline: 2.1449x; 1.3462x over previous
#include <cuda_runtime.h>
#include <cuda_bf16.h>
#include <mma.h>
#include <math.h>

using namespace nvcuda;

#define BB 4
#define LL 2048
#define KK 48
#define HH 128
#define NPAIR (BB*LL/2)
#define PGRID 304

// bf16 weights (node + edge MLPs) in global scratch
#define NB1   0
#define NB2   49152
#define NB3   65536
#define NB11  81920
#define NB12  131072
#define NB13  147456
#define NBTOT 163840
// tf32-f32 weights (FFN)
#define CWIN  0
#define CWOUT 65536
#define CWTOT 131072

__device__ __nv_bfloat16 g_wb[NBTOT];
__device__ float g_cw[CWTOT];
__device__ float g_v1[BB*LL*HH];   // h_V after node update + LN1
__device__ float g_v2[BB*LL*HH];   // h_V after FFN + LN2 + mask

// ---- persistent-CTA smem layout (bytes) ----
#define XLD2 264              // X tile stride (bf16 elems), K=256 +8 pad
#define FLD  132              // f32 staging stride (aliases X: 264*2 == 132*4)
#define HLD  136              // H tile / W2 / W3 stride (bf16)
#define OW1  0                // W1[e|nb] as B col-major: 128 cols x 264  = 67584 B
#define OW2  67584            // 128 x 136 bf16 = 34816 B
#define OW3  102400           // 34816 B
#define OX   137216           // 96 x 264 bf16 = 50688 B (aliases F 96x132 f32)
#define OH   187904           // 96 x 136 bf16 = 26112 B
#define OPV  214016           // 256 f32 = 1024 B
#define SMTOT 215040
#define NTHR 512

__device__ __forceinline__ float tf32r(float x){
    float r;
    asm("{\n .reg .b32 t;\n cvt.rna.tf32.f32 t, %1;\n mov.b32 %0, t;\n}"
        : "=f"(r) : "f"(x));
    return r;
}
__device__ __forceinline__ float gelu_f(float x){
    return 0.5f * x * (1.0f + erff(x * 0.7071067811865476f));
}

// pack 4 floats -> 4 bf16 (8B) store
__device__ __forceinline__ void st_bf4(__nv_bfloat16* p, float4 v){
    __nv_bfloat162 lo = __floats2bfloat162_rn(v.x, v.y);
    __nv_bfloat162 hi = __floats2bfloat162_rn(v.z, v.w);
    uint2 u; u.x = *(unsigned*)&lo; u.y = *(unsigned*)&hi;
    *(uint2*)p = u;
}

// ---------------------------------------------------------------------------
// Weight conversion
// ---------------------------------------------------------------------------
__global__ void cvt_weights(const float* __restrict__ w1, const float* __restrict__ w2,
                            const float* __restrict__ w3, const float* __restrict__ w11,
                            const float* __restrict__ w12, const float* __restrict__ w13,
                            const float* __restrict__ win, const float* __restrict__ wout){
    int i = blockIdx.x * blockDim.x + threadIdx.x;
    if (i < NBTOT){
        float v;
        if      (i < NB2)   v = w1[i - NB1];
        else if (i < NB3)   v = w2[i - NB2];
        else if (i < NB11)  v = w3[i - NB3];
        else if (i < NB12)  v = w11[i - NB11];
        else if (i < NB13)  v = w12[i - NB12];
        else                v = w13[i - NB13];
        g_wb[i] = __float2bfloat16(v);
    }
    if (i < CWTOT){
        float w = (i < CWOUT) ? win[i] : wout[i - CWOUT];
        g_cw[i] = tf32r(w);
    }
}

using FragA = wmma::fragment<wmma::matrix_a,16,16,16,__nv_bfloat16,wmma::row_major>;
using FragB = wmma::fragment<wmma::matrix_b,16,16,16,__nv_bfloat16,wmma::col_major>;
using FragC = wmma::fragment<wmma::accumulator,16,16,16,float>;

// Accumulator (lane,i)->(row,col) self-calibration.
__device__ __forceinline__ void calib_maps(float* scratch, int lane,
                                           unsigned& p0, unsigned& p1){
    for (int i = lane; i < 256; i += 32) scratch[i] = (float)i;
    __syncwarp();
    FragC f;
    wmma::load_matrix_sync(f, scratch, 16, wmma::mem_row_major);
    p0 = 0; p1 = 0;
#pragma unroll
    for (int i = 0; i < 4; i++) p0 |= ((unsigned)(int)f.x[i])     << (8 * i);
#pragma unroll
    for (int i = 0; i < 4; i++) p1 |= ((unsigned)(int)f.x[i + 4]) << (8 * i);
}

// 12-warp GEMM on 96-row tile: warp (mw 0..2, nw 0..3) -> 32x32 block.
template<int NK>
__device__ __forceinline__ void wg12(const __nv_bfloat16* As, int lda,
                                     const __nv_bfloat16* Bs, int ldb,
                                     FragC (&acc)[2][2], int mw, int nw){
#pragma unroll
    for (int t = 0; t < 2; t++)
#pragma unroll
        for (int u = 0; u < 2; u++) wmma::fill_fragment(acc[t][u], 0.0f);

    const __nv_bfloat16* B0 = Bs + (size_t)(nw * 32) * ldb;
    const __nv_bfloat16* B1 = B0 + (size_t)16 * ldb;
    const __nv_bfloat16* Am = As + (size_t)(mw * 32) * lda;

#pragma unroll 4
    for (int ks = 0; ks < NK; ks++){
        FragB b0, b1;
        wmma::load_matrix_sync(b0, B0 + ks * 16, ldb);
        wmma::load_matrix_sync(b1, B1 + ks * 16, ldb);
#pragma unroll
        for (int t = 0; t < 2; t++){
            FragA af;
            wmma::load_matrix_sync(af, Am + t * 16 * lda + ks * 16, lda);
            wmma::mma_sync(acc[t][0], af, b0, acc[t][0]);
            wmma::mma_sync(acc[t][1], af, b1, acc[t][1]);
        }
    }
}

// Fused epilogue: (+pv) + bias + gelu + bf16, registers -> smem dst.
__device__ __forceinline__ void epi_gelu(FragC (&acc)[2][2], __nv_bfloat16* dst, int ldd,
                                         const float* sbias, const float* pv,
                                         int mw, int nw, unsigned p0, unsigned p1){
#pragma unroll
    for (int t = 0; t < 2; t++)
#pragma unroll
        for (int u = 0; u < 2; u++){
            int rb = mw * 32 + t * 16, cb = nw * 32 + u * 16;
#pragma unroll
            for (int i = 0; i < 8; i++){
                unsigned v = ((i < 4 ? p0 : p1) >> (8 * (i & 3))) & 255u;
                int r = rb + (int)(v >> 4);
                int c = cb + (int)(v & 15u);
                float x = acc[t][u].x[i] + sbias[c];
                if (pv) x += pv[(r >= 48) * 128 + c];
                dst[r * ldd + c] = __float2bfloat16(gelu_f(x));
            }
        }
}

__device__ __forceinline__ void store_acc2(FragC (&acc)[2][2], float* F, int mw, int nw){
#pragma unroll
    for (int t = 0; t < 2; t++)
#pragma unroll
        for (int u = 0; u < 2; u++)
            wmma::store_matrix_sync(F + (size_t)(mw * 32 + t * 16) * FLD + nw * 32 + u * 16,
                                    acc[t][u], FLD, wmma::mem_row_major);
}

// Stage the three MLP weight matrices into smem (B col-major, padded strides).
__device__ __forceinline__ void stage_weights(char* smc, int woff1, int woff2, int woff3, int tid){
    for (int idx = tid; idx < 128 * 32; idx += NTHR){
        int o = idx >> 5, q = idx & 31;   // cols 128..383 of W row o
        *(uint4*)(smc + OW1 + o * (XLD2 * 2) + q * 16) =
            *(const uint4*)((const char*)(g_wb + woff1 + o * 384 + 128) + q * 16);
    }
    for (int idx = tid; idx < 128 * 16; idx += NTHR){
        int o = idx >> 4, q = idx & 15;
        *(uint4*)(smc + OW2 + o * (HLD * 2) + q * 16) =
            *(const uint4*)((const char*)(g_wb + woff2 + o * 128) + q * 16);
        *(uint4*)(smc + OW3 + o * (HLD * 2) + q * 16) =
            *(const uint4*)((const char*)(g_wb + woff3 + o * 128) + q * 16);
    }
}

// Vectorized gather of [96 x 256] = [hE | gathered nodes] into bf16 X tile.
__device__ __forceinline__ void gather_x(__nv_bfloat16* bfX, const float* __restrict__ eSrc,
                                         const float* __restrict__ vSrc,
                                         const int* __restrict__ Eidx, int nA, int tid){
#pragma unroll 2
    for (int i = tid; i < 96 * 64; i += NTHR){
        int r = i >> 6, c = (i & 63) * 4;
        int half = (r >= 48);
        int node = nA + half;
        int rr = r - half * 48;
        float4 v;
        if (c < 128){
            v = *(const float4*)&eSrc[((size_t)node * KK + rr) * HH + c];
        } else {
            int baseb = node & ~(LL - 1);
            int idx = __ldg(&Eidx[(size_t)node * KK + rr]);
            v = *(const float4*)&vSrc[((size_t)(baseb + idx)) * HH + (c - 128)];
        }
        st_bf4(&bfX[(size_t)r * XLD2 + c], v);
    }
}

// ---------------------------------------------------------------------------
// Kernel 1: node message MLP + masked k-sum + residual + LN1 -> g_v1
// ---------------------------------------------------------------------------
__global__ __launch_bounds__(NTHR, 1) void node_kernel(
    const float* __restrict__ hV, const float* __restrict__ hE,
    const int* __restrict__ Eidx, const float* __restrict__ mAtt,
    const float* __restrict__ W1f,
    const float* __restrict__ b1, const float* __restrict__ b2v, const float* __restrict__ b3,
    const float* __restrict__ g1, const float* __restrict__ lb1){
    extern __shared__ __align__(128) char smc[];
    __nv_bfloat16* sW1 = (__nv_bfloat16*)(smc + OW1);
    __nv_bfloat16* sW2 = (__nv_bfloat16*)(smc + OW2);
    __nv_bfloat16* sW3 = (__nv_bfloat16*)(smc + OW3);
    __nv_bfloat16* bfX = (__nv_bfloat16*)(smc + OX);
    float*         F   = (float*)(smc + OX);
    __nv_bfloat16* bfH = (__nv_bfloat16*)(smc + OH);
    float*         pv  = (float*)(smc + OPV);
    __shared__ float smask[96];
    __shared__ float sb_a[128], sb_b[128];
    __shared__ float red[2][8];
    __shared__ float bc[2][2];

    int tid = threadIdx.x, wid = tid >> 5, lane = tid & 31;
    int mw = wid >> 2, nw = wid & 3;           // compute warps: wid < 12

    unsigned p0, p1;
    calib_maps((float*)bfH + wid * 256, lane, p0, p1);

    stage_weights(smc, NB1, NB2, NB3, tid);
    if (tid < 128)                sb_a[tid] = b1[tid];
    else if (tid < 256)           sb_b[tid - 128] = b2v[tid - 128];

    for (int pair = blockIdx.x; pair < NPAIR; pair += gridDim.x){
        int nA = pair * 2;
        __syncthreads();   // prev iter done reading F / first iter: staging done

        gather_x(bfX, hE, hV, Eidx, nA, tid);
        if (tid < 96) smask[tid] = mAtt[(size_t)nA * KK + tid];
        __syncthreads();

        FragC acc[2][2];
        if (wid < 12){
            wg12<16>(bfX, XLD2, sW1, XLD2, acc, mw, nw);
        } else {
            // pv[j*128+o] = W1[:, 0:128] @ v_j  in f32 (exact path)
            int t = (wid - 12) * 32 + lane;   // 0..127
            const float4* Wr = (const float4*)(W1f + (size_t)t * 384);
            const float4* v0 = (const float4*)(hV + (size_t)nA * HH);
            const float4* v1 = (const float4*)(hV + (size_t)(nA + 1) * HH);
            float d0 = 0.f, d1 = 0.f;
#pragma unroll 8
            for (int q = 0; q < 32; q++){
                float4 w = Wr[q], a = v0[q], b = v1[q];
                d0 += w.x*a.x + w.y*a.y + w.z*a.z + w.w*a.w;
                d1 += w.x*b.x + w.y*b.y + w.z*b.z + w.w*b.w;
            }
            pv[t] = d0; pv[128 + t] = d1;
        }
        __syncthreads();
        if (wid < 12) epi_gelu(acc, bfH, HLD, sb_a, pv, mw, nw, p0, p1);
        __syncthreads();
        if (wid < 12) wg12<8>(bfH, HLD, sW2, HLD, acc, mw, nw);
        __syncthreads();
        if (wid < 12) epi_gelu(acc, bfH, HLD, sb_b, nullptr, mw, nw, p0, p1);
        __syncthreads();
        if (wid < 12){
            wg12<8>(bfH, HLD, sW3, HLD, acc, mw, nw);
            store_acc2(acc, F, mw, nw);
        }
        __syncthreads();

        // masked k-sum /30 + residual + per-node LN (first 256 threads)
        float t = 0.f; int j = 0, col = 0, node = nA;
        if (tid < 256){
            j = tid >> 7; col = tid & 127; node = nA + j;
            float b3c = b3[col], s = 0.f;
#pragma unroll 8
            for (int r = 0; r < KK; r++)
                s += smask[j * KK + r] * (F[(j * KK + r) * FLD + col] + b3c);
            t = hV[(size_t)node * HH + col] + s * (1.0f / 30.0f);
            float s1 = t, s2 = t * t;
#pragma unroll
            for (int o = 16; o; o >>= 1){
                s1 += __shfl_xor_sync(0xffffffffu, s1, o);
                s2 += __shfl_xor_sync(0xffffffffu, s2, o);
            }
            if (lane == 0){ red[0][wid] = s1; red[1][wid] = s2; }
        }
        __syncthreads();
        if (tid < 2){
            float a = 0.f, q = 0.f;
            for (int i = 0; i < 4; i++){ a += red[0][tid * 4 + i]; q += red[1][tid * 4 + i]; }
            float m = a * (1.f / 128.f);
            bc[tid][0] = m;
            bc[tid][1] = rsqrtf(q * (1.f / 128.f) - m * m + 1e-5f);
        }
        __syncthreads();
        if (tid < 256)
            g_v1[(size_t)node * HH + col] = (t - bc[j][0]) * bc[j][1] * g1[col] + lb1[col];
    }
}

// ---------------------------------------------------------------------------
// Kernel 2: position-wise FFN + residual + LN2 + mask_V (tf32, unchanged)
// ---------------------------------------------------------------------------
__global__ __launch_bounds__(256, 2) void ffn_kernel(
    const float* __restrict__ maskV,
    const float* __restrict__ winb, const float* __restrict__ woutb,
    const float* __restrict__ g2, const float* __restrict__ lb2,
    float* __restrict__ outV){
    extern __shared__ __align__(128) float sm[];
    float* Xv = sm;              // 64 x 136
    float* Hc = sm + 64 * 136;   // 64 x 136
    int tid = threadIdx.x, wid = tid >> 5, lane = tid & 31;
    int node0 = blockIdx.x * 64;

    for (int i = tid; i < 64 * 128; i += 256){
        int r = i >> 7, c = i & 127;
        Xv[r * 136 + c] = tf32r(g_v1[(size_t)(node0 + r) * HH + c]);
    }
    __syncthreads();

    int mt = wid & 3, ng = wid >> 2;
    int m0 = mt * 16;
    wmma::fragment<wmma::accumulator,16,16,8,float> accO[4];
#pragma unroll
    for (int j = 0; j < 4; j++) wmma::fill_fragment(accO[j], 0.0f);

    for (int ch = 0; ch < 4; ch++){
#pragma unroll
        for (int j = 0; j < 4; j++){
            int n0 = (ng * 4 + j) * 16;
            wmma::fragment<wmma::accumulator,16,16,8,float> c;
            wmma::fill_fragment(c, 0.0f);
            const float* Bp = g_cw + CWIN + ch * 128 * 128 + n0 * 128;
            wmma::fragment<wmma::matrix_b,16,16,8,wmma::precision::tf32,wmma::col_major> bf[2];
            wmma::load_matrix_sync(bf[0], Bp, 128);
#pragma unroll
            for (int ks = 0; ks < 16; ks++){
                if (ks + 1 < 16) wmma::load_matrix_sync(bf[(ks + 1) & 1], Bp + (ks + 1) * 8, 128);
                wmma::fragment<wmma::matrix_a,16,16,8,wmma::precision::tf32,wmma::row_major> af;
                wmma::load_matrix_sync(af, Xv + m0 * 136 + ks * 8, 136);
                wmma::mma_sync(c, af, bf[ks & 1], c);
            }
            wmma::store_matrix_sync(Hc + m0 * 136 + n0, c, 136, wmma::mem_row_major);
        }
        __syncthreads();
        for (int i = tid; i < 64 * 128; i += 256){
            int r = i >> 7, c = i & 127;
            Hc[r * 136 + c] = tf32r(gelu_f(Hc[r * 136 + c] + winb[ch * 128 + c]));
        }
        __syncthreads();
#pragma unroll
        for (int j = 0; j < 4; j++){
            int n0g = (ng * 4 + j) * 16;
            const float* Bp = g_cw + CWOUT + n0g * 512 + ch * 128;
            wmma::fragment<wmma::matrix_b,16,16,8,wmma::precision::tf32,wmma::col_major> bf[2];
            wmma::load_matrix_sync(bf[0], Bp, 512);
#pragma unroll
            for (int ks = 0; ks < 16; ks++){
                if (ks + 1 < 16) wmma::load_matrix_sync(bf[(ks + 1) & 1], Bp + (ks + 1) * 8, 512);
                wmma::fragment<wmma::matrix_a,16,16,8,wmma::precision::tf32,wmma::row_major> af;
                wmma::load_matrix_sync(af, Hc + m0 * 136 + ks * 8, 136);
                wmma::mma_sync(accO[j], af, bf[ks & 1], accO[j]);
            }
        }
        __syncthreads();
    }
#pragma unroll
    for (int j = 0; j < 4; j++)
        wmma::store_matrix_sync(Xv + m0 * 136 + (ng * 4 + j) * 16, accO[j], 136, wmma::mem_row_major);
    __syncthreads();

    for (int rr = 0; rr < 8; rr++){
        int r = wid * 8 + rr;
        int node = node0 + r;
        float mv = maskV[node];
        float v[4]; float s1 = 0.f, s2 = 0.f;
#pragma unroll
        for (int j = 0; j < 4; j++){
            int c = lane + j * 32;
            float x = g_v1[(size_t)node * HH + c] + Xv[r * 136 + c] + woutb[c];
            v[j] = x; s1 += x; s2 += x * x;
        }
#pragma unroll
        for (int o = 16; o; o >>= 1){
            s1 += __shfl_xor_sync(0xffffffffu, s1, o);
            s2 += __shfl_xor_sync(0xffffffffu, s2, o);
        }
        float m  = s1 * (1.f / 128.f);
        float rs = rsqrtf(s2 * (1.f / 128.f) - m * m + 1e-5f);
#pragma unroll
        for (int j = 0; j < 4; j++){
            int c = lane + j * 32;
            float o = mv * ((v[j] - m) * rs * g2[c] + lb2[c]);
            outV[(size_t)node * HH + c] = o;
            g_v2[(size_t)node * HH + c] = o;
        }
    }
}

// ---------------------------------------------------------------------------
// Kernel 3: edge message MLP + residual + LN3 -> out h_E (persistent)
// ---------------------------------------------------------------------------
__global__ __launch_bounds__(NTHR, 1) void edge_kernel(
    const float* __restrict__ hE, const int* __restrict__ Eidx,
    const float* __restrict__ W11f,
    const float* __restrict__ b11, const float* __restrict__ b12, const float* __restrict__ b13,
    const float* __restrict__ g3, const float* __restrict__ lb3,
    float* __restrict__ outE){
    extern __shared__ __align__(128) char smc[];
    __nv_bfloat16* sW1 = (__nv_bfloat16*)(smc + OW1);
    __nv_bfloat16* sW2 = (__nv_bfloat16*)(smc + OW2);
    __nv_bfloat16* sW3 = (__nv_bfloat16*)(smc + OW3);
    __nv_bfloat16* bfX = (__nv_bfloat16*)(smc + OX);
    float*         F   = (float*)(smc + OX);
    __nv_bfloat16* bfH = (__nv_bfloat16*)(smc + OH);
    float*         pv  = (float*)(smc + OPV);
    __shared__ float sb_a[128], sb_b[128];

    int tid = threadIdx.x, wid = tid >> 5, lane = tid & 31;
    int mw = wid >> 2, nw = wid & 3;

    unsigned p0, p1;
    calib_maps((float*)bfH + wid * 256, lane, p0, p1);

    stage_weights(smc, NB11, NB12, NB13, tid);
    if (tid < 128)      sb_a[tid] = b11[tid];
    else if (tid < 256) sb_b[tid - 128] = b12[tid - 128];

    for (int pair = blockIdx.x; pair < NPAIR; pair += gridDim.x){
        int nA = pair * 2;
        __syncthreads();

        gather_x(bfX, hE, g_v2, Eidx, nA, tid);
        __syncthreads();

        FragC acc[2][2];
        if (wid < 12){
            wg12<16>(bfX, XLD2, sW1, XLD2, acc, mw, nw);
        } else {
            int t = (wid - 12) * 32 + lane;
            const float4* Wr = (const float4*)(W11f + (size_t)t * 384);
            const float4* v0 = (const float4*)(g_v2 + (size_t)nA * HH);
            const float4* v1 = (const float4*)(g_v2 + (size_t)(nA + 1) * HH);
            float d0 = 0.f, d1 = 0.f;
#pragma unroll 8
            for (int q = 0; q < 32; q++){
                float4 w = Wr[q], a = v0[q], b = v1[q];
                d0 += w.x*a.x + w.y*a.y + w.z*a.z + w.w*a.w;
                d1 += w.x*b.x + w.y*b.y + w.z*b.z + w.w*b.w;
            }
            pv[t] = d0; pv[128 + t] = d1;
        }
        __syncthreads();
        if (wid < 12) epi_gelu(acc, bfH, HLD, sb_a, pv, mw, nw, p0, p1);
        __syncthreads();
        if (wid < 12) wg12<8>(bfH, HLD, sW2, HLD, acc, mw, nw);
        __syncthreads();
        if (wid < 12) epi_gelu(acc, bfH, HLD, sb_b, nullptr, mw, nw, p0, p1);
        __syncthreads();
        if (wid < 12){
            wg12<8>(bfH, HLD, sW3, HLD, acc, mw, nw);
            store_acc2(acc, F, mw, nw);
        }
        __syncthreads();

        // per-row residual + LN3: 16 warps x 6 rows, float4 per lane
        const float4 b4 = *(const float4*)&b13[lane * 4];
        const float4 g4 = *(const float4*)&g3[lane * 4];
        const float4 l4 = *(const float4*)&lb3[lane * 4];
#pragma unroll
        for (int rr = 0; rr < 6; rr++){
            int r = wid * 6 + rr;
            int half = (r >= 48);
            int node = nA + half;
            int er = r - half * 48;
            const float* her = hE + ((size_t)node * KK + er) * HH;
            float4 h4 = *(const float4*)&her[lane * 4];
            float4 f4 = *(const float4*)&F[r * FLD + lane * 4];
            float v0 = h4.x + f4.x + b4.x;
            float v1 = h4.y + f4.y + b4.y;
            float v2 = h4.z + f4.z + b4.z;
            float v3 = h4.w + f4.w + b4.w;
            float s1 = v0 + v1 + v2 + v3;
            float s2 = v0*v0 + v1*v1 + v2*v2 + v3*v3;
#pragma unroll
            for (int o = 16; o; o >>= 1){
                s1 += __shfl_xor_sync(0xffffffffu, s1, o);
                s2 += __shfl_xor_sync(0xffffffffu, s2, o);
            }
            float m  = s1 * (1.f / 128.f);
            float rs = rsqrtf(s2 * (1.f / 128.f) - m * m + 1e-5f);
            float4 o4;
            o4.x = (v0 - m) * rs * g4.x + l4.x;
            o4.y = (v1 - m) * rs * g4.y + l4.y;
            o4.z = (v2 - m) * rs * g4.z + l4.z;
            o4.w = (v3 - m) * rs * g4.w + l4.w;
            *(float4*)&outE[((size_t)node * KK + er) * HH + lane * 4] = o4;
        }
    }
}

// ---------------------------------------------------------------------------
extern "C" void kernel_launch(void* const* d_in, const int* in_sizes, int n_in,
                              void* d_out, int out_size){
    (void)in_sizes; (void)n_in; (void)out_size;
    const float* hV    = (const float*)d_in[0];
    const float* hE    = (const float*)d_in[1];
    const int*   Eidx  = (const int*)  d_in[2];
    const float* maskV = (const float*)d_in[3];
    const float* mAtt  = (const float*)d_in[4];
    const float* W1  = (const float*)d_in[5];  const float* b1  = (const float*)d_in[6];
    const float* W2  = (const float*)d_in[7];  const float* b2  = (const float*)d_in[8];
    const float* W3  = (const float*)d_in[9];  const float* b3  = (const float*)d_in[10];
    const float* W11 = (const float*)d_in[11]; const float* b11 = (const float*)d_in[12];
    const float* W12 = (const float*)d_in[13]; const float* b12 = (const float*)d_in[14];
    const float* W13 = (const float*)d_in[15]; const float* b13 = (const float*)d_in[16];
    const float* Win = (const float*)d_in[17]; const float* Winb = (const float*)d_in[18];
    const float* Wout= (const float*)d_in[19]; const float* Woutb= (const float*)d_in[20];
    const float* g1  = (const float*)d_in[21]; const float* lb1 = (const float*)d_in[22];
    const float* g2  = (const float*)d_in[23]; const float* lb2 = (const float*)d_in[24];
    const float* g3  = (const float*)d_in[25]; const float* lb3 = (const float*)d_in[26];

    float* outV = (float*)d_out;
    float* outE = outV + (size_t)BB * LL * HH;

    const int smem2 = 2 * 64 * 136 * 4;            // 69632 B
    cudaFuncSetAttribute(node_kernel, cudaFuncAttributeMaxDynamicSharedMemorySize, SMTOT);
    cudaFuncSetAttribute(edge_kernel, cudaFuncAttributeMaxDynamicSharedMemorySize, SMTOT);
    cudaFuncSetAttribute(ffn_kernel,  cudaFuncAttributeMaxDynamicSharedMemorySize, smem2);

    cvt_weights<<<(NBTOT + 255) / 256, 256>>>(W1, W2, W3, W11, W12, W13, Win, Wout);
    node_kernel<<<PGRID, NTHR, SMTOT>>>(hV, hE, Eidx, mAtt, W1, b1, b2, b3, g1, lb1);
    ffn_kernel<<<BB * LL / 64, 256, smem2>>>(maskV, Winb, Woutb, g2, lb2, outV);
    edge_kernel<<<PGRID, NTHR, SMTOT>>>(hE, Eidx, W11, b11, b12, b13, g3, lb3, outE);
}